// round 1
// baseline (speedup 1.0000x reference)
#include <cuda_runtime.h>

#define T_FRAMES 11
#define HID 1024
#define DQK 256
#define NTOT 1536           // 256 Q | 256 K | 1024 X
#define G 2                 // batches per CTA
#define ROWS (T_FRAMES * G) // 22
#define KT 128              // k tile
#define WSTR 132            // W tile row stride in floats (pad 4 -> conflict free)
#define LN_EPS 1e-5f

// shared memory layout (floats)
#define QKX_OFF 0
#define WT_OFF  (ROWS * NTOT)            // 33792
#define HT_OFF  (WT_OFF + 128 * WSTR)    // 33792 + 16896 = 50688
#define SC_OFF  (HT_OFF + ROWS * KT)     // 50688 + 2816  = 53504
#define SMEM_FLOATS (SC_OFF + G * T_FRAMES * 12)  // 53768 -> 215072 bytes

__device__ float g_W2[HID * HID];   // Wo @ Wv
__device__ float g_cvec[HID];       // Wo @ bv + bo

#define FMA4(c, a, b) do { \
    c = fmaf((a).x, (b).x, c); \
    c = fmaf((a).y, (b).y, c); \
    c = fmaf((a).z, (b).z, c); \
    c = fmaf((a).w, (b).w, c); } while (0)

// ---------------------------------------------------------------------------
// Prologue 1: W2 = Wo @ Wv   (1024x1024x1024 tiled SIMT GEMM)
// ---------------------------------------------------------------------------
__global__ __launch_bounds__(256) void w2_kernel(const float* __restrict__ Wo,
                                                 const float* __restrict__ Wv) {
    __shared__ float As[64][16];
    __shared__ float Bs[16][64];
    const int tid = threadIdx.x;
    const int tx = tid & 15, ty = tid >> 4;
    const int row0 = blockIdx.y * 64, col0 = blockIdx.x * 64;

    float acc[4][4] = {};
    for (int k0 = 0; k0 < HID; k0 += 16) {
        for (int i = tid; i < 1024; i += 256) {
            As[i >> 4][i & 15] = Wo[(size_t)(row0 + (i >> 4)) * HID + k0 + (i & 15)];
            Bs[i >> 6][i & 63] = Wv[(size_t)(k0 + (i >> 6)) * HID + col0 + (i & 63)];
        }
        __syncthreads();
        #pragma unroll
        for (int kk = 0; kk < 16; kk++) {
            float a0 = As[ty * 4 + 0][kk];
            float a1 = As[ty * 4 + 1][kk];
            float a2 = As[ty * 4 + 2][kk];
            float a3 = As[ty * 4 + 3][kk];
            float4 b = *(const float4*)&Bs[kk][tx * 4];
            acc[0][0] = fmaf(a0, b.x, acc[0][0]); acc[0][1] = fmaf(a0, b.y, acc[0][1]);
            acc[0][2] = fmaf(a0, b.z, acc[0][2]); acc[0][3] = fmaf(a0, b.w, acc[0][3]);
            acc[1][0] = fmaf(a1, b.x, acc[1][0]); acc[1][1] = fmaf(a1, b.y, acc[1][1]);
            acc[1][2] = fmaf(a1, b.z, acc[1][2]); acc[1][3] = fmaf(a1, b.w, acc[1][3]);
            acc[2][0] = fmaf(a2, b.x, acc[2][0]); acc[2][1] = fmaf(a2, b.y, acc[2][1]);
            acc[2][2] = fmaf(a2, b.z, acc[2][2]); acc[2][3] = fmaf(a2, b.w, acc[2][3]);
            acc[3][0] = fmaf(a3, b.x, acc[3][0]); acc[3][1] = fmaf(a3, b.y, acc[3][1]);
            acc[3][2] = fmaf(a3, b.z, acc[3][2]); acc[3][3] = fmaf(a3, b.w, acc[3][3]);
        }
        __syncthreads();
    }
    #pragma unroll
    for (int i = 0; i < 4; i++)
        #pragma unroll
        for (int j = 0; j < 4; j++)
            g_W2[(size_t)(row0 + ty * 4 + i) * HID + col0 + tx * 4 + j] = acc[i][j];
}

// ---------------------------------------------------------------------------
// Prologue 2: cvec = Wo @ bv + bo
// ---------------------------------------------------------------------------
__global__ void cvec_kernel(const float* __restrict__ Wo,
                            const float* __restrict__ bv,
                            const float* __restrict__ bo) {
    int o = blockIdx.x * blockDim.x + threadIdx.x;
    if (o < HID) {
        float s = 0.f;
        for (int m = 0; m < HID; m += 4) {
            float4 w = *(const float4*)(Wo + (size_t)o * HID + m);
            float4 b = *(const float4*)(bv + m);
            s = fmaf(w.x, b.x, s); s = fmaf(w.y, b.y, s);
            s = fmaf(w.z, b.z, s); s = fmaf(w.w, b.w, s);
        }
        g_cvec[o] = s + bo[o];
    }
}

// ---------------------------------------------------------------------------
// Main fused kernel: projections + attention + residual + layernorm
// 1 CTA = G(=2) batches = 22 token rows
// ---------------------------------------------------------------------------
__global__ __launch_bounds__(256, 1)
void fused_kernel(const float* __restrict__ h,
                  const float* __restrict__ Wq, const float* __restrict__ bq,
                  const float* __restrict__ Wk, const float* __restrict__ bk,
                  const float* __restrict__ gamma, const float* __restrict__ beta,
                  const float* __restrict__ screen_d, int n_screen,
                  const float* __restrict__ scale,
                  float* __restrict__ out) {
    extern __shared__ float smem[];
    float* qkx = smem + QKX_OFF;   // [22][1536]
    float* Wt  = smem + WT_OFF;    // [128][132]
    float* Ht  = smem + HT_OFF;    // [22][128]
    float* sc  = smem + SC_OFF;    // [2][11][12]

    const int tid = threadIdx.x;
    const long b0 = (long)blockIdx.x * G;
    const float* __restrict__ hsrc = h + b0 * T_FRAMES * HID;

    const int ct = tid & 31;        // col group: 4 consecutive cols
    const int rt = tid >> 5;        // row group: 3 rows
    const int r0 = rt * 3;
    const int hro0 = ((r0     < ROWS) ? r0     : ROWS - 1) * KT;
    const int hro1 = ((r0 + 1 < ROWS) ? r0 + 1 : ROWS - 1) * KT;
    const int hro2 = ((r0 + 2 < ROWS) ? r0 + 2 : ROWS - 1) * KT;
    const int wof  = ct * 4 * WSTR;

    // ================= GEMM: qkx[r][n] = sum_k h[r][k] * W[n][k] + bias =====
    for (int n0 = 0; n0 < NTOT; n0 += 128) {
        const float* wsrc;
        int nb;
        if (n0 < 256)      { wsrc = Wq;   nb = n0; }
        else if (n0 < 512) { wsrc = Wk;   nb = n0 - 256; }
        else               { wsrc = g_W2; nb = n0 - 512; }

        float4 wpre[16];
        float4 hpre[3];
        #pragma unroll
        for (int i = 0; i < 16; i++) {
            int idx = tid + i * 256;
            wpre[i] = *(const float4*)(wsrc + (size_t)(nb + (idx >> 5)) * HID + (idx & 31) * 4);
        }
        #pragma unroll
        for (int i = 0; i < 3; i++) {
            int idx = tid + i * 256;
            if (idx < ROWS * 32)
                hpre[i] = *(const float4*)(hsrc + (idx >> 5) * HID + (idx & 31) * 4);
        }

        float acc[3][4] = {};
        for (int kt = 0; kt < HID / KT; kt++) {
            __syncthreads();   // previous tile fully consumed
            #pragma unroll
            for (int i = 0; i < 16; i++) {
                int idx = tid + i * 256;
                *(float4*)(Wt + (idx >> 5) * WSTR + (idx & 31) * 4) = wpre[i];
            }
            #pragma unroll
            for (int i = 0; i < 3; i++) {
                int idx = tid + i * 256;
                if (idx < ROWS * 32)
                    *(float4*)(Ht + (idx >> 5) * KT + (idx & 31) * 4) = hpre[i];
            }
            __syncthreads();

            if (kt + 1 < HID / KT) {   // prefetch next k-tile into registers
                int ko = (kt + 1) * KT;
                #pragma unroll
                for (int i = 0; i < 16; i++) {
                    int idx = tid + i * 256;
                    wpre[i] = *(const float4*)(wsrc + (size_t)(nb + (idx >> 5)) * HID + ko + (idx & 31) * 4);
                }
                #pragma unroll
                for (int i = 0; i < 3; i++) {
                    int idx = tid + i * 256;
                    if (idx < ROWS * 32)
                        hpre[i] = *(const float4*)(hsrc + (idx >> 5) * HID + ko + (idx & 31) * 4);
                }
            }

            #pragma unroll 4
            for (int k = 0; k < KT; k += 4) {
                float4 a0 = *(const float4*)(Ht + hro0 + k);
                float4 a1 = *(const float4*)(Ht + hro1 + k);
                float4 a2 = *(const float4*)(Ht + hro2 + k);
                float4 w0 = *(const float4*)(Wt + wof + k);
                float4 w1 = *(const float4*)(Wt + wof + WSTR + k);
                float4 w2 = *(const float4*)(Wt + wof + 2 * WSTR + k);
                float4 w3 = *(const float4*)(Wt + wof + 3 * WSTR + k);
                FMA4(acc[0][0], a0, w0); FMA4(acc[0][1], a0, w1);
                FMA4(acc[0][2], a0, w2); FMA4(acc[0][3], a0, w3);
                FMA4(acc[1][0], a1, w0); FMA4(acc[1][1], a1, w1);
                FMA4(acc[1][2], a1, w2); FMA4(acc[1][3], a1, w3);
                FMA4(acc[2][0], a2, w0); FMA4(acc[2][1], a2, w1);
                FMA4(acc[2][2], a2, w2); FMA4(acc[2][3], a2, w3);
            }
        }

        #pragma unroll
        for (int j = 0; j < 4; j++) {
            int n = n0 + ct * 4 + j;
            float cb;
            if (n < 256)      cb = bq[n];
            else if (n < 512) cb = bk[n - 256];
            else              cb = g_cvec[n - 512];   // V/O biases folded in
            #pragma unroll
            for (int i = 0; i < 3; i++) {
                int r = r0 + i;
                if (r < ROWS) qkx[r * NTOT + n] = acc[i][j] + cb;
            }
        }
    }
    __syncthreads();

    // ================= scores + coulomb bias =================
    const float scl = scale[0];
    if (tid < G * 121) {
        int b = tid / 121, e = tid - b * 121;
        int i = e / 11, j = e - i * 11;
        const float4* q4 = (const float4*)(qkx + (b * T_FRAMES + i) * NTOT);
        const float4* k4 = (const float4*)(qkx + (b * T_FRAMES + j) * NTOT + DQK);
        float s = 0.f;
        #pragma unroll 8
        for (int k = 0; k < DQK / 4; k++) {
            float4 a = q4[k], bb = k4[k];
            s = fmaf(a.x, bb.x, s); s = fmaf(a.y, bb.y, s);
            s = fmaf(a.z, bb.z, s); s = fmaf(a.w, bb.w, s);
        }
        float r = fabsf((float)(i - j));
        float rr2 = r * r + 1e-6f;
        float wsum = 0.f, sg = 1.f;
        for (int kk = 0; kk < n_screen; kk++) {
            float d = screen_d[kk];
            wsum += sg * rsqrtf(d * d + rr2);
            sg = -sg;
        }
        sc[b * 132 + i * 12 + j] = s * 0.0625f + wsum / (scl + 1e-6f);
    }
    __syncthreads();

    // ================= softmax (one thread per row) =================
    if (tid < G * T_FRAMES) {
        float* row = sc + (tid / T_FRAMES) * 132 + (tid % T_FRAMES) * 12;
        float m = row[0];
        #pragma unroll
        for (int j = 1; j < 11; j++) m = fmaxf(m, row[j]);
        float sum = 0.f;
        #pragma unroll
        for (int j = 0; j < 11; j++) { float e = expf(row[j] - m); row[j] = e; sum += e; }
        float inv = 1.f / sum;
        #pragma unroll
        for (int j = 0; j < 11; j++) row[j] *= inv;
    }
    __syncthreads();

    // ================= A = P @ X, residual x = h + A (in place in X) ========
    #pragma unroll
    for (int it = 0; it < (G * HID) / 256; it++) {
        int idx = tid + it * 256;          // 0..2047
        int b = idx >> 10, c = idx & 1023;
        float xv[11];
        #pragma unroll
        for (int j = 0; j < 11; j++) xv[j] = qkx[(b * T_FRAMES + j) * NTOT + 512 + c];
        const float* P = sc + b * 132;
        #pragma unroll
        for (int i = 0; i < 11; i++) {
            float a = 0.f;
            #pragma unroll
            for (int j = 0; j < 11; j++) a = fmaf(P[i * 12 + j], xv[j], a);
            int r = b * T_FRAMES + i;
            qkx[r * NTOT + 512 + c] = hsrc[r * HID + c] + a;
        }
    }
    __syncthreads();

    // ================= layernorm + writeout (one warp per row) ==============
    {
        int w = tid >> 5, lane = tid & 31;
        for (int rr = w; rr < ROWS; rr += 8) {
            const float* xrow = qkx + rr * NTOT + 512;
            float s = 0.f, s2 = 0.f;
            for (int c = lane * 4; c < HID; c += 128) {
                float4 v = *(const float4*)(xrow + c);
                s  += v.x + v.y + v.z + v.w;
                s2 += v.x * v.x + v.y * v.y + v.z * v.z + v.w * v.w;
            }
            #pragma unroll
            for (int o = 16; o > 0; o >>= 1) {
                s  += __shfl_xor_sync(0xffffffffu, s, o);
                s2 += __shfl_xor_sync(0xffffffffu, s2, o);
            }
            float mu  = s * (1.f / HID);
            float var = s2 * (1.f / HID) - mu * mu;
            float rstd = rsqrtf(var + LN_EPS);
            float* orow = out + ((size_t)(b0 * T_FRAMES) + rr) * HID;
            for (int c = lane * 4; c < HID; c += 128) {
                float4 v = *(const float4*)(xrow + c);
                float4 g = *(const float4*)(gamma + c);
                float4 bb = *(const float4*)(beta + c);
                float4 o4;
                o4.x = (v.x - mu) * rstd * g.x + bb.x;
                o4.y = (v.y - mu) * rstd * g.y + bb.y;
                o4.z = (v.z - mu) * rstd * g.z + bb.z;
                o4.w = (v.w - mu) * rstd * g.w + bb.w;
                *(float4*)(orow + c) = o4;
            }
        }
    }
}

// ---------------------------------------------------------------------------
extern "C" void kernel_launch(void* const* d_in, const int* in_sizes, int n_in,
                              void* d_out, int out_size) {
    const float* h        = (const float*)d_in[0];
    const float* Wq       = (const float*)d_in[1];
    const float* bq       = (const float*)d_in[2];
    const float* Wk       = (const float*)d_in[3];
    const float* bk       = (const float*)d_in[4];
    const float* Wv       = (const float*)d_in[5];
    const float* bv       = (const float*)d_in[6];
    const float* Wo       = (const float*)d_in[7];
    const float* bo       = (const float*)d_in[8];
    const float* gamma    = (const float*)d_in[9];
    const float* beta     = (const float*)d_in[10];
    const float* screen_d = (const float*)d_in[11];
    const float* scale    = (const float*)d_in[12];
    int n_screen = in_sizes[11];
    int B = in_sizes[0] / (T_FRAMES * HID);
    float* out = (float*)d_out;

    w2_kernel<<<dim3(HID / 64, HID / 64), 256>>>(Wo, Wv);
    cvec_kernel<<<HID / 256, 256>>>(Wo, bv, bo);

    cudaFuncSetAttribute(fused_kernel, cudaFuncAttributeMaxDynamicSharedMemorySize,
                         SMEM_FLOATS * (int)sizeof(float));
    fused_kernel<<<B / G, 256, SMEM_FLOATS * sizeof(float)>>>(
        h, Wq, bq, Wk, bk, gamma, beta, screen_d, n_screen, scale, out);
}

// round 3
// speedup vs baseline: 10.1948x; 10.1948x over previous
#include <cuda_runtime.h>
#include <cuda_bf16.h>
#include <cstdint>

#define T_FRAMES 11
#define HID 1024
#define NTOT 1536
#define LN_EPS 1e-5f

// ===================== device scratch =====================
#define MROWS_MAX (8192L * T_FRAMES)          // 90112
__device__ __nv_bfloat16 g_h_hi[MROWS_MAX * HID];
__device__ __nv_bfloat16 g_h_lo[MROWS_MAX * HID];
__device__ __nv_bfloat16 g_W_hi[NTOT * HID];
__device__ __nv_bfloat16 g_W_lo[NTOT * HID];
__device__ float g_W2[HID * HID];
__device__ float g_bias[NTOT];
__device__ float g_qkx[MROWS_MAX * NTOT];

// ===================== PTX helpers (all base sm_80+ features) =====================
__device__ __forceinline__ uint32_t smem_u32(const void* p) {
    uint32_t a;
    asm("{ .reg .u64 t; cvta.to.shared.u64 t, %1; cvt.u32.u64 %0, t; }" : "=r"(a) : "l"(p));
    return a;
}
__device__ __forceinline__ void cp16(uint32_t dst, const void* src) {
    asm volatile("cp.async.cg.shared.global [%0], [%1], 16;" :: "r"(dst), "l"(src));
}
#define CP_COMMIT() asm volatile("cp.async.commit_group;" ::: "memory")
#define CP_WAIT2()  asm volatile("cp.async.wait_group 2;" ::: "memory")

__device__ __forceinline__ void ldsm4(uint32_t& r0, uint32_t& r1, uint32_t& r2, uint32_t& r3,
                                      uint32_t addr) {
    asm volatile("ldmatrix.sync.aligned.m8n8.x4.shared.b16 {%0,%1,%2,%3}, [%4];"
                 : "=r"(r0), "=r"(r1), "=r"(r2), "=r"(r3) : "r"(addr));
}
__device__ __forceinline__ void mma16816(float* c, const uint32_t* a, const uint32_t* b) {
    asm volatile(
        "mma.sync.aligned.m16n8k16.row.col.f32.bf16.bf16.f32 "
        "{%0,%1,%2,%3}, {%4,%5,%6,%7}, {%8,%9}, {%0,%1,%2,%3};"
        : "+f"(c[0]), "+f"(c[1]), "+f"(c[2]), "+f"(c[3])
        : "r"(a[0]), "r"(a[1]), "r"(a[2]), "r"(a[3]), "r"(b[0]), "r"(b[1]));
}

// ===================== prologue kernels =====================
__global__ __launch_bounds__(256) void w2_kernel(const float* __restrict__ Wo,
                                                 const float* __restrict__ Wv) {
    __shared__ float As[64][16];
    __shared__ float Bs[16][64];
    const int tid = threadIdx.x;
    const int tx = tid & 15, ty = tid >> 4;
    const int row0 = blockIdx.y * 64, col0 = blockIdx.x * 64;
    float acc[4][4] = {};
    for (int k0 = 0; k0 < HID; k0 += 16) {
        for (int i = tid; i < 1024; i += 256) {
            As[i >> 4][i & 15] = Wo[(size_t)(row0 + (i >> 4)) * HID + k0 + (i & 15)];
            Bs[i >> 6][i & 63] = Wv[(size_t)(k0 + (i >> 6)) * HID + col0 + (i & 63)];
        }
        __syncthreads();
        #pragma unroll
        for (int kk = 0; kk < 16; kk++) {
            float a0 = As[ty*4+0][kk], a1 = As[ty*4+1][kk], a2 = As[ty*4+2][kk], a3 = As[ty*4+3][kk];
            float4 b = *(const float4*)&Bs[kk][tx*4];
            acc[0][0]=fmaf(a0,b.x,acc[0][0]); acc[0][1]=fmaf(a0,b.y,acc[0][1]); acc[0][2]=fmaf(a0,b.z,acc[0][2]); acc[0][3]=fmaf(a0,b.w,acc[0][3]);
            acc[1][0]=fmaf(a1,b.x,acc[1][0]); acc[1][1]=fmaf(a1,b.y,acc[1][1]); acc[1][2]=fmaf(a1,b.z,acc[1][2]); acc[1][3]=fmaf(a1,b.w,acc[1][3]);
            acc[2][0]=fmaf(a2,b.x,acc[2][0]); acc[2][1]=fmaf(a2,b.y,acc[2][1]); acc[2][2]=fmaf(a2,b.z,acc[2][2]); acc[2][3]=fmaf(a2,b.w,acc[2][3]);
            acc[3][0]=fmaf(a3,b.x,acc[3][0]); acc[3][1]=fmaf(a3,b.y,acc[3][1]); acc[3][2]=fmaf(a3,b.z,acc[3][2]); acc[3][3]=fmaf(a3,b.w,acc[3][3]);
        }
        __syncthreads();
    }
    #pragma unroll
    for (int i = 0; i < 4; i++)
        #pragma unroll
        for (int j = 0; j < 4; j++)
            g_W2[(size_t)(row0 + ty*4 + i) * HID + col0 + tx*4 + j] = acc[i][j];
}

__global__ void cvec_kernel(const float* __restrict__ Wo, const float* __restrict__ bv,
                            const float* __restrict__ bo) {
    int o = blockIdx.x * blockDim.x + threadIdx.x;
    if (o < HID) {
        float s = 0.f;
        for (int m = 0; m < HID; m += 4) {
            float4 w = *(const float4*)(Wo + (size_t)o * HID + m);
            float4 b = *(const float4*)(bv + m);
            s = fmaf(w.x,b.x,s); s = fmaf(w.y,b.y,s); s = fmaf(w.z,b.z,s); s = fmaf(w.w,b.w,s);
        }
        g_bias[512 + o] = s + bo[o];
    }
}

__device__ __forceinline__ void split4(float4 v, uint2& hi, uint2& lo) {
    float h0 = __bfloat162float(__float2bfloat16(v.x));
    float h1 = __bfloat162float(__float2bfloat16(v.y));
    float h2 = __bfloat162float(__float2bfloat16(v.z));
    float h3 = __bfloat162float(__float2bfloat16(v.w));
    union { __nv_bfloat162 b[2]; uint2 u; } ph, pl;
    ph.b[0] = __floats2bfloat162_rn(h0, h1);
    ph.b[1] = __floats2bfloat162_rn(h2, h3);
    pl.b[0] = __floats2bfloat162_rn(v.x - h0, v.y - h1);
    pl.b[1] = __floats2bfloat162_rn(v.z - h2, v.w - h3);
    hi = ph.u; lo = pl.u;
}

__global__ __launch_bounds__(256) void prep_w_kernel(const float* __restrict__ Wq,
                                                     const float* __restrict__ Wk,
                                                     const float* __restrict__ bq,
                                                     const float* __restrict__ bk) {
    int i = blockIdx.x * 256 + threadIdx.x;        // over 1536*1024/4 float4s
    int row = i >> 8, c4 = i & 255;
    const float* src = (row < 256) ? Wq + (size_t)row * HID
                     : (row < 512) ? Wk + (size_t)(row - 256) * HID
                                   : g_W2 + (size_t)(row - 512) * HID;
    float4 v = ((const float4*)src)[c4];
    uint2 hi, lo; split4(v, hi, lo);
    ((uint2*)g_W_hi)[i] = hi;
    ((uint2*)g_W_lo)[i] = lo;
    if (i < 128)
        ((float4*)g_bias)[i] = (i < 64) ? ((const float4*)bq)[i] : ((const float4*)bk)[i - 64];
}

__global__ __launch_bounds__(256) void convert_h_kernel(const float* __restrict__ h) {
    long i = (long)blockIdx.x * 256 + threadIdx.x; // over M*HID/4 float4s
    float4 v = ((const float4*)h)[i];
    uint2 hi, lo; split4(v, hi, lo);
    ((uint2*)g_h_hi)[i] = hi;
    ((uint2*)g_h_lo)[i] = lo;
}

// ===================== mma.sync GEMM: QKX = h * W^T + bias =====================
// CTA 128x128, BK=64, 3-stage cp.async pipeline, 8 warps (2m x 4n), warp 64x32.
#define BK 64
#define NKS (HID / BK)             // 16
#define MAT_B 16384                // 128 rows x 64 bf16 = 16KB per matrix
#define STAGE_B (4 * MAT_B)        // Ah|Al|Bh|Bl = 64KB
#define GEMM_SMEM (3 * STAGE_B)    // 192KB

__device__ __forceinline__ uint32_t swz(uint32_t byte) {
    return byte ^ ((byte >> 3) & 0x70);
}

__global__ __launch_bounds__(256, 1) void gemm_kernel() {
    extern __shared__ __align__(1024) char sm[];
    const int tid = threadIdx.x, wid = tid >> 5, lane = tid & 31;
    const long m0 = (long)blockIdx.y * 128;
    const long n0 = (long)blockIdx.x * 128;
    const int m_w = (wid & 1) * 64;       // warp M offset
    const int n_w = (wid >> 1) * 32;      // warp N offset
    const uint32_t sb = smem_u32(sm);

    const __nv_bfloat16* __restrict__ Ah = g_h_hi + m0 * HID;
    const __nv_bfloat16* __restrict__ Al = g_h_lo + m0 * HID;
    const __nv_bfloat16* __restrict__ Bh = g_W_hi + n0 * HID;
    const __nv_bfloat16* __restrict__ Bl = g_W_lo + n0 * HID;

    // per-thread cp.async mapping: 4 chunks per matrix per stage
    const int crow = tid >> 3;            // base row (we add i*32)
    const int ckc  = tid & 7;             // 16B chunk within 128B row

    // prologue: stages 0..2
    #pragma unroll
    for (int s = 0; s < 3; s++) {
        uint32_t st = sb + s * STAGE_B;
        int ko = s * BK;
        #pragma unroll
        for (int i = 0; i < 4; i++) {
            int row = crow + i * 32;
            uint32_t sw = swz(row * 128 + ckc * 16);
            size_t go = (size_t)row * HID + ko + ckc * 8;
            cp16(st + sw,             Ah + go);
            cp16(st + MAT_B + sw,     Al + go);
            cp16(st + 2 * MAT_B + sw, Bh + go);
            cp16(st + 3 * MAT_B + sw, Bl + go);
        }
        CP_COMMIT();
    }

    float acc[4][4][4] = {};   // [mt][nt][reg]

    for (int ks = 0; ks < NKS; ks++) {
        CP_WAIT2();
        __syncthreads();
        const uint32_t st = sb + (ks % 3) * STAGE_B;

        #pragma unroll
        for (int kk = 0; kk < BK / 16; kk++) {
            uint32_t ah[4][4], al[4][4], bh[4][2], bl[4][2];
            // A fragments: 4 m-tiles, hi+lo
            #pragma unroll
            for (int mt = 0; mt < 4; mt++) {
                uint32_t byte = (uint32_t)(m_w + mt * 16 + (lane & 15)) * 128
                              + kk * 32 + ((lane >> 4) << 4);
                uint32_t sw = swz(byte);
                ldsm4(ah[mt][0], ah[mt][1], ah[mt][2], ah[mt][3], st + sw);
                ldsm4(al[mt][0], al[mt][1], al[mt][2], al[mt][3], st + MAT_B + sw);
            }
            // B fragments: 4 n-tiles (two x4 loads), hi+lo
            #pragma unroll
            for (int half = 0; half < 2; half++) {
                int grp = lane >> 3;
                uint32_t rowB = (uint32_t)(n_w + half * 16 + ((grp & 2) << 2) + (lane & 7));
                uint32_t byte = rowB * 128 + kk * 32 + ((grp & 1) << 4);
                uint32_t sw = swz(byte);
                ldsm4(bh[half*2][0], bh[half*2][1], bh[half*2+1][0], bh[half*2+1][1],
                      st + 2 * MAT_B + sw);
                ldsm4(bl[half*2][0], bl[half*2][1], bl[half*2+1][0], bl[half*2+1][1],
                      st + 3 * MAT_B + sw);
            }
            // 3-term split MMA
            #pragma unroll
            for (int mt = 0; mt < 4; mt++)
                #pragma unroll
                for (int nt = 0; nt < 4; nt++) {
                    mma16816(acc[mt][nt], ah[mt], bh[nt]);
                    mma16816(acc[mt][nt], ah[mt], bl[nt]);
                    mma16816(acc[mt][nt], al[mt], bh[nt]);
                }
        }
        __syncthreads();   // all warps done with this buffer

        if (ks + 3 < NKS) {
            uint32_t st2 = sb + (ks % 3) * STAGE_B;
            int ko = (ks + 3) * BK;
            #pragma unroll
            for (int i = 0; i < 4; i++) {
                int row = crow + i * 32;
                uint32_t sw = swz(row * 128 + ckc * 16);
                size_t go = (size_t)row * HID + ko + ckc * 8;
                cp16(st2 + sw,             Ah + go);
                cp16(st2 + MAT_B + sw,     Al + go);
                cp16(st2 + 2 * MAT_B + sw, Bh + go);
                cp16(st2 + 3 * MAT_B + sw, Bl + go);
            }
        }
        CP_COMMIT();       // empty groups near the tail keep wait_group math valid
    }

    // epilogue: D + bias -> g_qkx (fp32)
    const int qrow = lane >> 2;            // 0..7
    const int qcol = 2 * (lane & 3);       // 0,2,4,6
    #pragma unroll
    for (int nt = 0; nt < 4; nt++) {
        const int col = (int)n0 + n_w + nt * 8 + qcol;
        const float2 bv = *(const float2*)(g_bias + col);
        #pragma unroll
        for (int mt = 0; mt < 4; mt++) {
            long r0 = m0 + m_w + mt * 16 + qrow;
            float2 v0 = { acc[mt][nt][0] + bv.x, acc[mt][nt][1] + bv.y };
            float2 v1 = { acc[mt][nt][2] + bv.x, acc[mt][nt][3] + bv.y };
            *(float2*)(g_qkx + r0 * NTOT + col)       = v0;
            *(float2*)(g_qkx + (r0 + 8) * NTOT + col) = v1;
        }
    }
}

// ===================== attention + softmax + residual + LN =====================
#define QKSTR 516
#define ATTN_SMEM ((11*QKSTR + 11*1024 + 132) * 4)

__global__ __launch_bounds__(256) void attn_kernel(const float* __restrict__ h,
                                                   const float* __restrict__ gamma,
                                                   const float* __restrict__ beta,
                                                   const float* __restrict__ screen_d, int n_screen,
                                                   const float* __restrict__ scale,
                                                   float* __restrict__ out) {
    extern __shared__ float sa[];
    float* qk = sa;                    // [11][516]: Q at +0, K at +256
    float* xs = sa + 11 * QKSTR;       // [11][1024]
    float* sc = xs + 11 * 1024;        // [11][12]
    const int tid = threadIdx.x;
    const long b = blockIdx.x;
    const float* __restrict__ qkxb = g_qkx + b * T_FRAMES * NTOT;
    const float* __restrict__ hb = h + b * T_FRAMES * HID;

    for (int idx = tid; idx < 11 * 128; idx += 256) {
        int r = idx >> 7, c = idx & 127;
        ((float4*)(qk + r * QKSTR))[c] = ((const float4*)qkxb)[r * 384 + c];
    }
    __syncthreads();

    const float scl = scale[0];
    if (tid < 121) {
        int i = tid / 11, j = tid - i * 11;
        const float4* q4 = (const float4*)(qk + i * QKSTR);
        const float4* k4 = (const float4*)(qk + j * QKSTR + 256);
        float s = 0.f;
        #pragma unroll 8
        for (int k = 0; k < 64; k++) {
            float4 a = q4[k], bb = k4[k];
            s = fmaf(a.x,bb.x,s); s = fmaf(a.y,bb.y,s); s = fmaf(a.z,bb.z,s); s = fmaf(a.w,bb.w,s);
        }
        float r = fabsf((float)(i - j));
        float rr2 = r * r + 1e-6f;
        float wsum = 0.f, sg = 1.f;
        for (int kk = 0; kk < n_screen; kk++) {
            float d = screen_d[kk];
            wsum += sg * rsqrtf(d * d + rr2);
            sg = -sg;
        }
        sc[i * 12 + j] = s * 0.0625f + wsum / (scl + 1e-6f);
    }
    __syncthreads();

    if (tid < T_FRAMES) {
        float* row = sc + tid * 12;
        float m = row[0];
        #pragma unroll
        for (int j = 1; j < 11; j++) m = fmaxf(m, row[j]);
        float sum = 0.f;
        #pragma unroll
        for (int j = 0; j < 11; j++) { float e = expf(row[j] - m); row[j] = e; sum += e; }
        float inv = 1.f / sum;
        #pragma unroll
        for (int j = 0; j < 11; j++) row[j] *= inv;
    }
    __syncthreads();

    #pragma unroll
    for (int it = 0; it < 4; it++) {
        int c = tid + it * 256;
        float xv[11];
        #pragma unroll
        for (int j = 0; j < 11; j++) xv[j] = qkxb[j * NTOT + 512 + c];
        #pragma unroll
        for (int i = 0; i < 11; i++) {
            float a = 0.f;
            #pragma unroll
            for (int j = 0; j < 11; j++) a = fmaf(sc[i * 12 + j], xv[j], a);
            xs[i * 1024 + c] = hb[i * HID + c] + a;
        }
    }
    __syncthreads();

    const int w = tid >> 5, lane = tid & 31;
    for (int rr = w; rr < T_FRAMES; rr += 8) {
        const float* xrow = xs + rr * 1024;
        float s = 0.f, s2 = 0.f;
        for (int c = lane * 4; c < HID; c += 128) {
            float4 v = *(const float4*)(xrow + c);
            s  += v.x + v.y + v.z + v.w;
            s2 += v.x*v.x + v.y*v.y + v.z*v.z + v.w*v.w;
        }
        #pragma unroll
        for (int o = 16; o > 0; o >>= 1) {
            s  += __shfl_xor_sync(0xffffffffu, s, o);
            s2 += __shfl_xor_sync(0xffffffffu, s2, o);
        }
        float mu = s * (1.f / HID);
        float var = s2 * (1.f / HID) - mu * mu;
        float rstd = rsqrtf(var + LN_EPS);
        float* orow = out + (b * T_FRAMES + rr) * HID;
        for (int c = lane * 4; c < HID; c += 128) {
            float4 v = *(const float4*)(xrow + c);
            float4 g = *(const float4*)(gamma + c);
            float4 bb = *(const float4*)(beta + c);
            float4 o4;
            o4.x = (v.x - mu) * rstd * g.x + bb.x;
            o4.y = (v.y - mu) * rstd * g.y + bb.y;
            o4.z = (v.z - mu) * rstd * g.z + bb.z;
            o4.w = (v.w - mu) * rstd * g.w + bb.w;
            *(float4*)(orow + c) = o4;
        }
    }
}

// ===================== launch =====================
extern "C" void kernel_launch(void* const* d_in, const int* in_sizes, int n_in,
                              void* d_out, int out_size) {
    const float* h        = (const float*)d_in[0];
    const float* Wq       = (const float*)d_in[1];
    const float* bq       = (const float*)d_in[2];
    const float* Wk       = (const float*)d_in[3];
    const float* bk       = (const float*)d_in[4];
    const float* Wv       = (const float*)d_in[5];
    const float* bv       = (const float*)d_in[6];
    const float* Wo       = (const float*)d_in[7];
    const float* bo       = (const float*)d_in[8];
    const float* gamma    = (const float*)d_in[9];
    const float* beta     = (const float*)d_in[10];
    const float* screen_d = (const float*)d_in[11];
    const float* scale    = (const float*)d_in[12];
    const int n_screen = in_sizes[11];
    const long B = in_sizes[0] / (T_FRAMES * HID);
    const long M = B * T_FRAMES;                    // 90112
    float* out = (float*)d_out;

    cudaFuncSetAttribute(gemm_kernel, cudaFuncAttributeMaxDynamicSharedMemorySize, GEMM_SMEM);
    cudaFuncSetAttribute(attn_kernel, cudaFuncAttributeMaxDynamicSharedMemorySize, ATTN_SMEM);

    w2_kernel<<<dim3(HID / 64, HID / 64), 256>>>(Wo, Wv);
    cvec_kernel<<<HID / 256, 256>>>(Wo, bv, bo);
    prep_w_kernel<<<(NTOT * HID / 4) / 256, 256>>>(Wq, Wk, bq, bk);
    convert_h_kernel<<<(unsigned)((M * HID / 4) / 256), 256>>>(h);

    dim3 ggrid(NTOT / 128, (unsigned)(M / 128));
    gemm_kernel<<<ggrid, 256, GEMM_SMEM>>>();

    attn_kernel<<<(unsigned)B, 256, ATTN_SMEM>>>(h, gamma, beta, screen_d, n_screen, scale, out);
}

// round 4
// speedup vs baseline: 13.3476x; 1.3093x over previous
#include <cuda_runtime.h>
#include <cuda_bf16.h>
#include <cstdint>

#define T_FRAMES 11
#define HID 1024
#define NTOT 1536
#define LN_EPS 1e-5f

// ===================== device scratch =====================
#define MROWS_MAX (8192L * T_FRAMES)          // 90112
__device__ __nv_bfloat16 g_h_hi[MROWS_MAX * HID];
__device__ __nv_bfloat16 g_W_hi[NTOT * HID];
__device__ __nv_bfloat16 g_W_lo[NTOT * HID];
__device__ float g_W2[HID * HID];
__device__ float g_w2p[8][HID * HID];          // split-K partials
__device__ float g_bias[NTOT];
__device__ float g_qkx[MROWS_MAX * NTOT];

// ===================== PTX helpers (base sm_80+ features only) =====================
__device__ __forceinline__ uint32_t smem_u32(const void* p) {
    uint32_t a;
    asm("{ .reg .u64 t; cvta.to.shared.u64 t, %1; cvt.u32.u64 %0, t; }" : "=r"(a) : "l"(p));
    return a;
}
__device__ __forceinline__ void cp16(uint32_t dst, const void* src) {
    asm volatile("cp.async.cg.shared.global [%0], [%1], 16;" :: "r"(dst), "l"(src));
}
#define CP_COMMIT() asm volatile("cp.async.commit_group;" ::: "memory")
#define CP_WAIT2()  asm volatile("cp.async.wait_group 2;" ::: "memory")

__device__ __forceinline__ void ldsm4(uint32_t& r0, uint32_t& r1, uint32_t& r2, uint32_t& r3,
                                      uint32_t addr) {
    asm volatile("ldmatrix.sync.aligned.m8n8.x4.shared.b16 {%0,%1,%2,%3}, [%4];"
                 : "=r"(r0), "=r"(r1), "=r"(r2), "=r"(r3) : "r"(addr));
}
__device__ __forceinline__ void mma16816(float* c, const uint32_t* a, const uint32_t* b) {
    asm volatile(
        "mma.sync.aligned.m16n8k16.row.col.f32.bf16.bf16.f32 "
        "{%0,%1,%2,%3}, {%4,%5,%6,%7}, {%8,%9}, {%0,%1,%2,%3};"
        : "+f"(c[0]), "+f"(c[1]), "+f"(c[2]), "+f"(c[3])
        : "r"(a[0]), "r"(a[1]), "r"(a[2]), "r"(a[3]), "r"(b[0]), "r"(b[1]));
}

// ===================== prologue: W2 = Wo @ Wv, split-K x8 =====================
__global__ __launch_bounds__(256) void w2_part_kernel(const float* __restrict__ Wo,
                                                      const float* __restrict__ Wv) {
    __shared__ float As[64][16];
    __shared__ float Bs[16][64];
    const int tid = threadIdx.x;
    const int tx = tid & 15, ty = tid >> 4;
    const int row0 = blockIdx.y * 64, col0 = blockIdx.x * 64;
    const int kbase = blockIdx.z * 128;
    float acc[4][4] = {};
    for (int k0 = kbase; k0 < kbase + 128; k0 += 16) {
        for (int i = tid; i < 1024; i += 256) {
            As[i >> 4][i & 15] = Wo[(size_t)(row0 + (i >> 4)) * HID + k0 + (i & 15)];
            Bs[i >> 6][i & 63] = Wv[(size_t)(k0 + (i >> 6)) * HID + col0 + (i & 63)];
        }
        __syncthreads();
        #pragma unroll
        for (int kk = 0; kk < 16; kk++) {
            float a0 = As[ty*4+0][kk], a1 = As[ty*4+1][kk], a2 = As[ty*4+2][kk], a3 = As[ty*4+3][kk];
            float4 b = *(const float4*)&Bs[kk][tx*4];
            acc[0][0]=fmaf(a0,b.x,acc[0][0]); acc[0][1]=fmaf(a0,b.y,acc[0][1]); acc[0][2]=fmaf(a0,b.z,acc[0][2]); acc[0][3]=fmaf(a0,b.w,acc[0][3]);
            acc[1][0]=fmaf(a1,b.x,acc[1][0]); acc[1][1]=fmaf(a1,b.y,acc[1][1]); acc[1][2]=fmaf(a1,b.z,acc[1][2]); acc[1][3]=fmaf(a1,b.w,acc[1][3]);
            acc[2][0]=fmaf(a2,b.x,acc[2][0]); acc[2][1]=fmaf(a2,b.y,acc[2][1]); acc[2][2]=fmaf(a2,b.z,acc[2][2]); acc[2][3]=fmaf(a2,b.w,acc[2][3]);
            acc[3][0]=fmaf(a3,b.x,acc[3][0]); acc[3][1]=fmaf(a3,b.y,acc[3][1]); acc[3][2]=fmaf(a3,b.z,acc[3][2]); acc[3][3]=fmaf(a3,b.w,acc[3][3]);
        }
        __syncthreads();
    }
    float* dst = g_w2p[blockIdx.z];
    #pragma unroll
    for (int i = 0; i < 4; i++)
        #pragma unroll
        for (int j = 0; j < 4; j++)
            dst[(size_t)(row0 + ty*4 + i) * HID + col0 + tx*4 + j] = acc[i][j];
}

__global__ __launch_bounds__(256) void w2_reduce_kernel() {
    int i = blockIdx.x * 256 + threadIdx.x;   // over HID*HID/4 float4s
    float4 s = ((const float4*)g_w2p[0])[i];
    #pragma unroll
    for (int z = 1; z < 8; z++) {
        float4 p = ((const float4*)g_w2p[z])[i];
        s.x += p.x; s.y += p.y; s.z += p.z; s.w += p.w;
    }
    ((float4*)g_W2)[i] = s;
}

__global__ void cvec_kernel(const float* __restrict__ Wo, const float* __restrict__ bv,
                            const float* __restrict__ bo) {
    int o = blockIdx.x * blockDim.x + threadIdx.x;
    if (o < HID) {
        float s = 0.f;
        for (int m = 0; m < HID; m += 4) {
            float4 w = *(const float4*)(Wo + (size_t)o * HID + m);
            float4 b = *(const float4*)(bv + m);
            s = fmaf(w.x,b.x,s); s = fmaf(w.y,b.y,s); s = fmaf(w.z,b.z,s); s = fmaf(w.w,b.w,s);
        }
        g_bias[512 + o] = s + bo[o];
    }
}

__device__ __forceinline__ void split4(float4 v, uint2& hi, uint2& lo) {
    float h0 = __bfloat162float(__float2bfloat16(v.x));
    float h1 = __bfloat162float(__float2bfloat16(v.y));
    float h2 = __bfloat162float(__float2bfloat16(v.z));
    float h3 = __bfloat162float(__float2bfloat16(v.w));
    union { __nv_bfloat162 b[2]; uint2 u; } ph, pl;
    ph.b[0] = __floats2bfloat162_rn(h0, h1);
    ph.b[1] = __floats2bfloat162_rn(h2, h3);
    pl.b[0] = __floats2bfloat162_rn(v.x - h0, v.y - h1);
    pl.b[1] = __floats2bfloat162_rn(v.z - h2, v.w - h3);
    hi = ph.u; lo = pl.u;
}

__global__ __launch_bounds__(256) void prep_w_kernel(const float* __restrict__ Wq,
                                                     const float* __restrict__ Wk,
                                                     const float* __restrict__ bq,
                                                     const float* __restrict__ bk) {
    int i = blockIdx.x * 256 + threadIdx.x;        // over 1536*1024/4 float4s
    int row = i >> 8, c4 = i & 255;
    const float* src = (row < 256) ? Wq + (size_t)row * HID
                     : (row < 512) ? Wk + (size_t)(row - 256) * HID
                                   : g_W2 + (size_t)(row - 512) * HID;
    float4 v = ((const float4*)src)[c4];
    uint2 hi, lo; split4(v, hi, lo);
    ((uint2*)g_W_hi)[i] = hi;
    ((uint2*)g_W_lo)[i] = lo;
    if (i < 128)
        ((float4*)g_bias)[i] = (i < 64) ? ((const float4*)bq)[i] : ((const float4*)bk)[i - 64];
}

// h -> bf16 hi only (2-term scheme keeps full precision on W side)
__global__ __launch_bounds__(256) void convert_h_kernel(const float* __restrict__ h) {
    long i = (long)blockIdx.x * 256 + threadIdx.x; // over M*HID/4 float4s
    float4 v = ((const float4*)h)[i];
    union { __nv_bfloat162 b[2]; uint2 u; } ph;
    ph.b[0] = __floats2bfloat162_rn(v.x, v.y);
    ph.b[1] = __floats2bfloat162_rn(v.z, v.w);
    ((uint2*)g_h_hi)[i] = ph.u;
}

// ===================== mma.sync GEMM: QKX = h * W^T + bias =====================
// CTA 128x128, BK=64, 3-stage cp.async pipeline, 8 warps (2m x 4n), warp 64x32.
// D = Ah*Bh + Ah*Bl  (2-term split; A lo dropped)
#define BK 64
#define NKS (HID / BK)             // 16
#define MAT_B 16384                // 128 rows x 64 bf16 = 16KB per matrix
#define STAGE_B (3 * MAT_B)        // Ah|Bh|Bl = 48KB
#define GEMM_SMEM (3 * STAGE_B)    // 144KB

__device__ __forceinline__ uint32_t swz(uint32_t byte) {
    return byte ^ ((byte >> 3) & 0x70);
}

__global__ __launch_bounds__(256, 1) void gemm_kernel() {
    extern __shared__ __align__(1024) char sm[];
    const int tid = threadIdx.x, wid = tid >> 5, lane = tid & 31;
    const long m0 = (long)blockIdx.y * 128;
    const long n0 = (long)blockIdx.x * 128;
    const int m_w = (wid & 1) * 64;       // warp M offset
    const int n_w = (wid >> 1) * 32;      // warp N offset
    const uint32_t sb = smem_u32(sm);

    const __nv_bfloat16* __restrict__ Ah = g_h_hi + m0 * HID;
    const __nv_bfloat16* __restrict__ Bh = g_W_hi + n0 * HID;
    const __nv_bfloat16* __restrict__ Bl = g_W_lo + n0 * HID;

    const int crow = tid >> 3;            // base row (we add i*32)
    const int ckc  = tid & 7;             // 16B chunk within 128B row

    #pragma unroll
    for (int s = 0; s < 3; s++) {
        uint32_t st = sb + s * STAGE_B;
        int ko = s * BK;
        #pragma unroll
        for (int i = 0; i < 4; i++) {
            int row = crow + i * 32;
            uint32_t sw = swz(row * 128 + ckc * 16);
            size_t go = (size_t)row * HID + ko + ckc * 8;
            cp16(st + sw,             Ah + go);
            cp16(st + MAT_B + sw,     Bh + go);
            cp16(st + 2 * MAT_B + sw, Bl + go);
        }
        CP_COMMIT();
    }

    float acc[4][4][4] = {};   // [mt][nt][reg]

    for (int ks = 0; ks < NKS; ks++) {
        CP_WAIT2();
        __syncthreads();
        const uint32_t st = sb + (ks % 3) * STAGE_B;

        #pragma unroll
        for (int kk = 0; kk < BK / 16; kk++) {
            uint32_t ah[4][4], bh[4][2], bl[4][2];
            #pragma unroll
            for (int mt = 0; mt < 4; mt++) {
                uint32_t byte = (uint32_t)(m_w + mt * 16 + (lane & 15)) * 128
                              + kk * 32 + ((lane >> 4) << 4);
                uint32_t sw = swz(byte);
                ldsm4(ah[mt][0], ah[mt][1], ah[mt][2], ah[mt][3], st + sw);
            }
            #pragma unroll
            for (int half = 0; half < 2; half++) {
                int grp = lane >> 3;
                uint32_t rowB = (uint32_t)(n_w + half * 16 + ((grp & 2) << 2) + (lane & 7));
                uint32_t byte = rowB * 128 + kk * 32 + ((grp & 1) << 4);
                uint32_t sw = swz(byte);
                ldsm4(bh[half*2][0], bh[half*2][1], bh[half*2+1][0], bh[half*2+1][1],
                      st + MAT_B + sw);
                ldsm4(bl[half*2][0], bl[half*2][1], bl[half*2+1][0], bl[half*2+1][1],
                      st + 2 * MAT_B + sw);
            }
            #pragma unroll
            for (int mt = 0; mt < 4; mt++)
                #pragma unroll
                for (int nt = 0; nt < 4; nt++) {
                    mma16816(acc[mt][nt], ah[mt], bh[nt]);
                    mma16816(acc[mt][nt], ah[mt], bl[nt]);
                }
        }
        __syncthreads();

        if (ks + 3 < NKS) {
            uint32_t st2 = sb + (ks % 3) * STAGE_B;
            int ko = (ks + 3) * BK;
            #pragma unroll
            for (int i = 0; i < 4; i++) {
                int row = crow + i * 32;
                uint32_t sw = swz(row * 128 + ckc * 16);
                size_t go = (size_t)row * HID + ko + ckc * 8;
                cp16(st2 + sw,             Ah + go);
                cp16(st2 + MAT_B + sw,     Bh + go);
                cp16(st2 + 2 * MAT_B + sw, Bl + go);
            }
        }
        CP_COMMIT();
    }

    // epilogue: D + bias -> g_qkx (fp32)
    const int qrow = lane >> 2;            // 0..7
    const int qcol = 2 * (lane & 3);       // 0,2,4,6
    #pragma unroll
    for (int nt = 0; nt < 4; nt++) {
        const int col = (int)n0 + n_w + nt * 8 + qcol;
        const float2 bv = *(const float2*)(g_bias + col);
        #pragma unroll
        for (int mt = 0; mt < 4; mt++) {
            long r0 = m0 + m_w + mt * 16 + qrow;
            float2 v0 = { acc[mt][nt][0] + bv.x, acc[mt][nt][1] + bv.y };
            float2 v1 = { acc[mt][nt][2] + bv.x, acc[mt][nt][3] + bv.y };
            *(float2*)(g_qkx + r0 * NTOT + col)       = v0;
            *(float2*)(g_qkx + (r0 + 8) * NTOT + col) = v1;
        }
    }
}

// ===================== attention + softmax + residual + LN =====================
#define QKSTR 516
#define ATTN_SMEM ((11*QKSTR + 11*1024 + 132) * 4)

__global__ __launch_bounds__(256) void attn_kernel(const float* __restrict__ h,
                                                   const float* __restrict__ gamma,
                                                   const float* __restrict__ beta,
                                                   const float* __restrict__ screen_d, int n_screen,
                                                   const float* __restrict__ scale,
                                                   float* __restrict__ out) {
    extern __shared__ float sa[];
    float* qk = sa;                    // [11][516]: Q at +0, K at +256
    float* xs = sa + 11 * QKSTR;       // [11][1024]
    float* sc = xs + 11 * 1024;        // [11][12]
    const int tid = threadIdx.x;
    const long b = blockIdx.x;
    const float* __restrict__ qkxb = g_qkx + b * T_FRAMES * NTOT;
    const float* __restrict__ hb = h + b * T_FRAMES * HID;

    for (int idx = tid; idx < 11 * 128; idx += 256) {
        int r = idx >> 7, c = idx & 127;
        ((float4*)(qk + r * QKSTR))[c] = ((const float4*)qkxb)[r * 384 + c];
    }
    __syncthreads();

    const float scl = scale[0];
    if (tid < 121) {
        int i = tid / 11, j = tid - i * 11;
        const float4* q4 = (const float4*)(qk + i * QKSTR);
        const float4* k4 = (const float4*)(qk + j * QKSTR + 256);
        float s = 0.f;
        #pragma unroll 8
        for (int k = 0; k < 64; k++) {
            float4 a = q4[k], bb = k4[k];
            s = fmaf(a.x,bb.x,s); s = fmaf(a.y,bb.y,s); s = fmaf(a.z,bb.z,s); s = fmaf(a.w,bb.w,s);
        }
        float r = fabsf((float)(i - j));
        float rr2 = r * r + 1e-6f;
        float wsum = 0.f, sg = 1.f;
        for (int kk = 0; kk < n_screen; kk++) {
            float d = screen_d[kk];
            wsum += sg * rsqrtf(d * d + rr2);
            sg = -sg;
        }
        sc[i * 12 + j] = s * 0.0625f + wsum / (scl + 1e-6f);
    }
    __syncthreads();

    if (tid < T_FRAMES) {
        float* row = sc + tid * 12;
        float m = row[0];
        #pragma unroll
        for (int j = 1; j < 11; j++) m = fmaxf(m, row[j]);
        float sum = 0.f;
        #pragma unroll
        for (int j = 0; j < 11; j++) { float e = expf(row[j] - m); row[j] = e; sum += e; }
        float inv = 1.f / sum;
        #pragma unroll
        for (int j = 0; j < 11; j++) row[j] *= inv;
    }
    __syncthreads();

    #pragma unroll
    for (int it = 0; it < 4; it++) {
        int c = tid + it * 256;
        float xv[11];
        #pragma unroll
        for (int j = 0; j < 11; j++) xv[j] = qkxb[j * NTOT + 512 + c];
        #pragma unroll
        for (int i = 0; i < 11; i++) {
            float a = 0.f;
            #pragma unroll
            for (int j = 0; j < 11; j++) a = fmaf(sc[i * 12 + j], xv[j], a);
            xs[i * 1024 + c] = hb[i * HID + c] + a;
        }
    }
    __syncthreads();

    const int w = tid >> 5, lane = tid & 31;
    for (int rr = w; rr < T_FRAMES; rr += 8) {
        const float* xrow = xs + rr * 1024;
        float s = 0.f, s2 = 0.f;
        for (int c = lane * 4; c < HID; c += 128) {
            float4 v = *(const float4*)(xrow + c);
            s  += v.x + v.y + v.z + v.w;
            s2 += v.x*v.x + v.y*v.y + v.z*v.z + v.w*v.w;
        }
        #pragma unroll
        for (int o = 16; o > 0; o >>= 1) {
            s  += __shfl_xor_sync(0xffffffffu, s, o);
            s2 += __shfl_xor_sync(0xffffffffu, s2, o);
        }
        float mu = s * (1.f / HID);
        float var = s2 * (1.f / HID) - mu * mu;
        float rstd = rsqrtf(var + LN_EPS);
        float* orow = out + (b * T_FRAMES + rr) * HID;
        for (int c = lane * 4; c < HID; c += 128) {
            float4 v = *(const float4*)(xrow + c);
            float4 g = *(const float4*)(gamma + c);
            float4 bb = *(const float4*)(beta + c);
            float4 o4;
            o4.x = (v.x - mu) * rstd * g.x + bb.x;
            o4.y = (v.y - mu) * rstd * g.y + bb.y;
            o4.z = (v.z - mu) * rstd * g.z + bb.z;
            o4.w = (v.w - mu) * rstd * g.w + bb.w;
            *(float4*)(orow + c) = o4;
        }
    }
}

// ===================== launch =====================
extern "C" void kernel_launch(void* const* d_in, const int* in_sizes, int n_in,
                              void* d_out, int out_size) {
    const float* h        = (const float*)d_in[0];
    const float* Wq       = (const float*)d_in[1];
    const float* bq       = (const float*)d_in[2];
    const float* Wk       = (const float*)d_in[3];
    const float* bk       = (const float*)d_in[4];
    const float* Wv       = (const float*)d_in[5];
    const float* bv       = (const float*)d_in[6];
    const float* Wo       = (const float*)d_in[7];
    const float* bo       = (const float*)d_in[8];
    const float* gamma    = (const float*)d_in[9];
    const float* beta     = (const float*)d_in[10];
    const float* screen_d = (const float*)d_in[11];
    const float* scale    = (const float*)d_in[12];
    const int n_screen = in_sizes[11];
    const long B = in_sizes[0] / (T_FRAMES * HID);
    const long M = B * T_FRAMES;                    // 90112
    float* out = (float*)d_out;

    cudaFuncSetAttribute(gemm_kernel, cudaFuncAttributeMaxDynamicSharedMemorySize, GEMM_SMEM);
    cudaFuncSetAttribute(attn_kernel, cudaFuncAttributeMaxDynamicSharedMemorySize, ATTN_SMEM);

    w2_part_kernel<<<dim3(HID / 64, HID / 64, 8), 256>>>(Wo, Wv);
    w2_reduce_kernel<<<(HID * HID / 4) / 256, 256>>>();
    cvec_kernel<<<HID / 256, 256>>>(Wo, bv, bo);
    prep_w_kernel<<<(NTOT * HID / 4) / 256, 256>>>(Wq, Wk, bq, bk);
    convert_h_kernel<<<(unsigned)((M * HID / 4) / 256), 256>>>(h);

    dim3 ggrid(NTOT / 128, (unsigned)(M / 128));
    gemm_kernel<<<ggrid, 256, GEMM_SMEM>>>();

    attn_kernel<<<(unsigned)B, 256, ATTN_SMEM>>>(h, gamma, beta, screen_d, n_screen, scale, out);
}

// round 5
// speedup vs baseline: 20.9887x; 1.5725x over previous
#include <cuda_runtime.h>
#include <cuda_bf16.h>
#include <cstdint>

#define T_FRAMES 11
#define HID 1024
#define NTOT 1536
#define LN_EPS 1e-5f

// ===================== device scratch =====================
#define MROWS_MAX (8192L * T_FRAMES)          // 90112
__device__ __nv_bfloat16 g_h_hi[MROWS_MAX * HID];
__device__ __nv_bfloat16 g_W_hi[NTOT * HID];
__device__ float g_W2[HID * HID];
__device__ float g_w2p[8][HID * HID];          // split-K partials
__device__ float g_bias[NTOT];
__device__ float g_qkx[MROWS_MAX * NTOT];

// ===================== PTX helpers (base sm_80+ features only) =====================
__device__ __forceinline__ uint32_t smem_u32(const void* p) {
    uint32_t a;
    asm("{ .reg .u64 t; cvta.to.shared.u64 t, %1; cvt.u32.u64 %0, t; }" : "=r"(a) : "l"(p));
    return a;
}
__device__ __forceinline__ void cp16(uint32_t dst, const void* src) {
    asm volatile("cp.async.cg.shared.global [%0], [%1], 16;" :: "r"(dst), "l"(src));
}
#define CP_COMMIT() asm volatile("cp.async.commit_group;" ::: "memory")
#define CP_WAIT2()  asm volatile("cp.async.wait_group 2;" ::: "memory")

__device__ __forceinline__ void ldsm4(uint32_t& r0, uint32_t& r1, uint32_t& r2, uint32_t& r3,
                                      uint32_t addr) {
    asm volatile("ldmatrix.sync.aligned.m8n8.x4.shared.b16 {%0,%1,%2,%3}, [%4];"
                 : "=r"(r0), "=r"(r1), "=r"(r2), "=r"(r3) : "r"(addr));
}
__device__ __forceinline__ void mma16816(float* c, const uint32_t* a, const uint32_t* b) {
    asm volatile(
        "mma.sync.aligned.m16n8k16.row.col.f32.bf16.bf16.f32 "
        "{%0,%1,%2,%3}, {%4,%5,%6,%7}, {%8,%9}, {%0,%1,%2,%3};"
        : "+f"(c[0]), "+f"(c[1]), "+f"(c[2]), "+f"(c[3])
        : "r"(a[0]), "r"(a[1]), "r"(a[2]), "r"(a[3]), "r"(b[0]), "r"(b[1]));
}

// ===================== prologue: W2 = Wo @ Wv, split-K x8 =====================
__global__ __launch_bounds__(256) void w2_part_kernel(const float* __restrict__ Wo,
                                                      const float* __restrict__ Wv) {
    __shared__ float As[64][16];
    __shared__ float Bs[16][64];
    const int tid = threadIdx.x;
    const int tx = tid & 15, ty = tid >> 4;
    const int row0 = blockIdx.y * 64, col0 = blockIdx.x * 64;
    const int kbase = blockIdx.z * 128;
    float acc[4][4] = {};
    for (int k0 = kbase; k0 < kbase + 128; k0 += 16) {
        for (int i = tid; i < 1024; i += 256) {
            As[i >> 4][i & 15] = Wo[(size_t)(row0 + (i >> 4)) * HID + k0 + (i & 15)];
            Bs[i >> 6][i & 63] = Wv[(size_t)(k0 + (i >> 6)) * HID + col0 + (i & 63)];
        }
        __syncthreads();
        #pragma unroll
        for (int kk = 0; kk < 16; kk++) {
            float a0 = As[ty*4+0][kk], a1 = As[ty*4+1][kk], a2 = As[ty*4+2][kk], a3 = As[ty*4+3][kk];
            float4 b = *(const float4*)&Bs[kk][tx*4];
            acc[0][0]=fmaf(a0,b.x,acc[0][0]); acc[0][1]=fmaf(a0,b.y,acc[0][1]); acc[0][2]=fmaf(a0,b.z,acc[0][2]); acc[0][3]=fmaf(a0,b.w,acc[0][3]);
            acc[1][0]=fmaf(a1,b.x,acc[1][0]); acc[1][1]=fmaf(a1,b.y,acc[1][1]); acc[1][2]=fmaf(a1,b.z,acc[1][2]); acc[1][3]=fmaf(a1,b.w,acc[1][3]);
            acc[2][0]=fmaf(a2,b.x,acc[2][0]); acc[2][1]=fmaf(a2,b.y,acc[2][1]); acc[2][2]=fmaf(a2,b.z,acc[2][2]); acc[2][3]=fmaf(a2,b.w,acc[2][3]);
            acc[3][0]=fmaf(a3,b.x,acc[3][0]); acc[3][1]=fmaf(a3,b.y,acc[3][1]); acc[3][2]=fmaf(a3,b.z,acc[3][2]); acc[3][3]=fmaf(a3,b.w,acc[3][3]);
        }
        __syncthreads();
    }
    float* dst = g_w2p[blockIdx.z];
    #pragma unroll
    for (int i = 0; i < 4; i++)
        #pragma unroll
        for (int j = 0; j < 4; j++)
            dst[(size_t)(row0 + ty*4 + i) * HID + col0 + tx*4 + j] = acc[i][j];
}

__global__ __launch_bounds__(256) void w2_reduce_kernel() {
    int i = blockIdx.x * 256 + threadIdx.x;   // over HID*HID/4 float4s
    float4 s = ((const float4*)g_w2p[0])[i];
    #pragma unroll
    for (int z = 1; z < 8; z++) {
        float4 p = ((const float4*)g_w2p[z])[i];
        s.x += p.x; s.y += p.y; s.z += p.z; s.w += p.w;
    }
    ((float4*)g_W2)[i] = s;
}

__global__ void cvec_kernel(const float* __restrict__ Wo, const float* __restrict__ bv,
                            const float* __restrict__ bo) {
    int o = blockIdx.x * blockDim.x + threadIdx.x;
    if (o < HID) {
        float s = 0.f;
        for (int m = 0; m < HID; m += 4) {
            float4 w = *(const float4*)(Wo + (size_t)o * HID + m);
            float4 b = *(const float4*)(bv + m);
            s = fmaf(w.x,b.x,s); s = fmaf(w.y,b.y,s); s = fmaf(w.z,b.z,s); s = fmaf(w.w,b.w,s);
        }
        g_bias[512 + o] = s + bo[o];
    }
}

// W -> bf16 (plain round-to-nearest)
__global__ __launch_bounds__(256) void prep_w_kernel(const float* __restrict__ Wq,
                                                     const float* __restrict__ Wk,
                                                     const float* __restrict__ bq,
                                                     const float* __restrict__ bk) {
    int i = blockIdx.x * 256 + threadIdx.x;        // over 1536*1024/4 float4s
    int row = i >> 8, c4 = i & 255;
    const float* src = (row < 256) ? Wq + (size_t)row * HID
                     : (row < 512) ? Wk + (size_t)(row - 256) * HID
                                   : g_W2 + (size_t)(row - 512) * HID;
    float4 v = ((const float4*)src)[c4];
    union { __nv_bfloat162 b[2]; uint2 u; } ph;
    ph.b[0] = __floats2bfloat162_rn(v.x, v.y);
    ph.b[1] = __floats2bfloat162_rn(v.z, v.w);
    ((uint2*)g_W_hi)[i] = ph.u;
    if (i < 128)
        ((float4*)g_bias)[i] = (i < 64) ? ((const float4*)bq)[i] : ((const float4*)bk)[i - 64];
}

// h -> bf16
__global__ __launch_bounds__(256) void convert_h_kernel(const float* __restrict__ h) {
    long i = (long)blockIdx.x * 256 + threadIdx.x; // over M*HID/4 float4s
    float4 v = ((const float4*)h)[i];
    union { __nv_bfloat162 b[2]; uint2 u; } ph;
    ph.b[0] = __floats2bfloat162_rn(v.x, v.y);
    ph.b[1] = __floats2bfloat162_rn(v.z, v.w);
    ((uint2*)g_h_hi)[i] = ph.u;
}

// ===================== mma.sync GEMM: QKX = h * W^T + bias =====================
// CTA 128x128, BK=64, 3-stage cp.async pipeline, 8 warps (2m x 4n), warp 64x32.
// Plain bf16 x bf16 (1 term). 2 CTAs/SM.
#define BK 64
#define NKS (HID / BK)             // 16
#define MAT_B 16384                // 128 rows x 64 bf16 = 16KB per matrix
#define STAGE_B (2 * MAT_B)        // Ah|Bh = 32KB
#define GEMM_SMEM (3 * STAGE_B)    // 96KB

__device__ __forceinline__ uint32_t swz(uint32_t byte) {
    return byte ^ ((byte >> 3) & 0x70);
}

__global__ __launch_bounds__(256, 2) void gemm_kernel() {
    extern __shared__ __align__(1024) char sm[];
    const int tid = threadIdx.x, wid = tid >> 5, lane = tid & 31;
    const long m0 = (long)blockIdx.y * 128;
    const long n0 = (long)blockIdx.x * 128;
    const int m_w = (wid & 1) * 64;       // warp M offset
    const int n_w = (wid >> 1) * 32;      // warp N offset
    const uint32_t sb = smem_u32(sm);

    const __nv_bfloat16* __restrict__ Ah = g_h_hi + m0 * HID;
    const __nv_bfloat16* __restrict__ Bh = g_W_hi + n0 * HID;

    const int crow = tid >> 3;            // base row (we add i*32)
    const int ckc  = tid & 7;             // 16B chunk within 128B row

    #pragma unroll
    for (int s = 0; s < 3; s++) {
        uint32_t st = sb + s * STAGE_B;
        int ko = s * BK;
        #pragma unroll
        for (int i = 0; i < 4; i++) {
            int row = crow + i * 32;
            uint32_t sw = swz(row * 128 + ckc * 16);
            size_t go = (size_t)row * HID + ko + ckc * 8;
            cp16(st + sw,         Ah + go);
            cp16(st + MAT_B + sw, Bh + go);
        }
        CP_COMMIT();
    }

    float acc[4][4][4] = {};   // [mt][nt][reg]

    for (int ks = 0; ks < NKS; ks++) {
        CP_WAIT2();
        __syncthreads();
        const uint32_t st = sb + (ks % 3) * STAGE_B;

        #pragma unroll
        for (int kk = 0; kk < BK / 16; kk++) {
            uint32_t ah[4][4], bh[4][2];
            #pragma unroll
            for (int mt = 0; mt < 4; mt++) {
                uint32_t byte = (uint32_t)(m_w + mt * 16 + (lane & 15)) * 128
                              + kk * 32 + ((lane >> 4) << 4);
                uint32_t sw = swz(byte);
                ldsm4(ah[mt][0], ah[mt][1], ah[mt][2], ah[mt][3], st + sw);
            }
            #pragma unroll
            for (int half = 0; half < 2; half++) {
                int grp = lane >> 3;
                uint32_t rowB = (uint32_t)(n_w + half * 16 + ((grp & 2) << 2) + (lane & 7));
                uint32_t byte = rowB * 128 + kk * 32 + ((grp & 1) << 4);
                uint32_t sw = swz(byte);
                ldsm4(bh[half*2][0], bh[half*2][1], bh[half*2+1][0], bh[half*2+1][1],
                      st + MAT_B + sw);
            }
            #pragma unroll
            for (int mt = 0; mt < 4; mt++)
                #pragma unroll
                for (int nt = 0; nt < 4; nt++)
                    mma16816(acc[mt][nt], ah[mt], bh[nt]);
        }
        __syncthreads();

        if (ks + 3 < NKS) {
            uint32_t st2 = sb + (ks % 3) * STAGE_B;
            int ko = (ks + 3) * BK;
            #pragma unroll
            for (int i = 0; i < 4; i++) {
                int row = crow + i * 32;
                uint32_t sw = swz(row * 128 + ckc * 16);
                size_t go = (size_t)row * HID + ko + ckc * 8;
                cp16(st2 + sw,         Ah + go);
                cp16(st2 + MAT_B + sw, Bh + go);
            }
        }
        CP_COMMIT();
    }

    // epilogue: D + bias -> g_qkx (fp32)
    const int qrow = lane >> 2;            // 0..7
    const int qcol = 2 * (lane & 3);       // 0,2,4,6
    #pragma unroll
    for (int nt = 0; nt < 4; nt++) {
        const int col = (int)n0 + n_w + nt * 8 + qcol;
        const float2 bv = *(const float2*)(g_bias + col);
        #pragma unroll
        for (int mt = 0; mt < 4; mt++) {
            long r0 = m0 + m_w + mt * 16 + qrow;
            float2 v0 = { acc[mt][nt][0] + bv.x, acc[mt][nt][1] + bv.y };
            float2 v1 = { acc[mt][nt][2] + bv.x, acc[mt][nt][3] + bv.y };
            *(float2*)(g_qkx + r0 * NTOT + col)       = v0;
            *(float2*)(g_qkx + (r0 + 8) * NTOT + col) = v1;
        }
    }
}

// ===================== attention + softmax + residual + LN =====================
#define QKSTR 516
#define ATTN_SMEM ((11*QKSTR + 11*1024 + 132) * 4)

__global__ __launch_bounds__(256) void attn_kernel(const float* __restrict__ h,
                                                   const float* __restrict__ gamma,
                                                   const float* __restrict__ beta,
                                                   const float* __restrict__ screen_d, int n_screen,
                                                   const float* __restrict__ scale,
                                                   float* __restrict__ out) {
    extern __shared__ float sa[];
    float* qk = sa;                    // [11][516]: Q at +0, K at +256
    float* xs = sa + 11 * QKSTR;       // [11][1024]
    float* sc = xs + 11 * 1024;        // [11][12]
    const int tid = threadIdx.x;
    const long b = blockIdx.x;
    const float* __restrict__ qkxb = g_qkx + b * T_FRAMES * NTOT;
    const float* __restrict__ hb = h + b * T_FRAMES * HID;

    for (int idx = tid; idx < 11 * 128; idx += 256) {
        int r = idx >> 7, c = idx & 127;
        ((float4*)(qk + r * QKSTR))[c] = ((const float4*)qkxb)[r * 384 + c];
    }
    __syncthreads();

    const float scl = scale[0];
    if (tid < 121) {
        int i = tid / 11, j = tid - i * 11;
        const float4* q4 = (const float4*)(qk + i * QKSTR);
        const float4* k4 = (const float4*)(qk + j * QKSTR + 256);
        float s = 0.f;
        #pragma unroll 8
        for (int k = 0; k < 64; k++) {
            float4 a = q4[k], bb = k4[k];
            s = fmaf(a.x,bb.x,s); s = fmaf(a.y,bb.y,s); s = fmaf(a.z,bb.z,s); s = fmaf(a.w,bb.w,s);
        }
        float r = fabsf((float)(i - j));
        float rr2 = r * r + 1e-6f;
        float wsum = 0.f, sg = 1.f;
        for (int kk = 0; kk < n_screen; kk++) {
            float d = screen_d[kk];
            wsum += sg * rsqrtf(d * d + rr2);
            sg = -sg;
        }
        sc[i * 12 + j] = s * 0.0625f + wsum / (scl + 1e-6f);
    }
    __syncthreads();

    if (tid < T_FRAMES) {
        float* row = sc + tid * 12;
        float m = row[0];
        #pragma unroll
        for (int j = 1; j < 11; j++) m = fmaxf(m, row[j]);
        float sum = 0.f;
        #pragma unroll
        for (int j = 0; j < 11; j++) { float e = expf(row[j] - m); row[j] = e; sum += e; }
        float inv = 1.f / sum;
        #pragma unroll
        for (int j = 0; j < 11; j++) row[j] *= inv;
    }
    __syncthreads();

    #pragma unroll
    for (int it = 0; it < 4; it++) {
        int c = tid + it * 256;
        float xv[11];
        #pragma unroll
        for (int j = 0; j < 11; j++) xv[j] = qkxb[j * NTOT + 512 + c];
        #pragma unroll
        for (int i = 0; i < 11; i++) {
            float a = 0.f;
            #pragma unroll
            for (int j = 0; j < 11; j++) a = fmaf(sc[i * 12 + j], xv[j], a);
            xs[i * 1024 + c] = hb[i * HID + c] + a;
        }
    }
    __syncthreads();

    const int w = tid >> 5, lane = tid & 31;
    for (int rr = w; rr < T_FRAMES; rr += 8) {
        const float* xrow = xs + rr * 1024;
        float s = 0.f, s2 = 0.f;
        for (int c = lane * 4; c < HID; c += 128) {
            float4 v = *(const float4*)(xrow + c);
            s  += v.x + v.y + v.z + v.w;
            s2 += v.x*v.x + v.y*v.y + v.z*v.z + v.w*v.w;
        }
        #pragma unroll
        for (int o = 16; o > 0; o >>= 1) {
            s  += __shfl_xor_sync(0xffffffffu, s, o);
            s2 += __shfl_xor_sync(0xffffffffu, s2, o);
        }
        float mu = s * (1.f / HID);
        float var = s2 * (1.f / HID) - mu * mu;
        float rstd = rsqrtf(var + LN_EPS);
        float* orow = out + (b * T_FRAMES + rr) * HID;
        for (int c = lane * 4; c < HID; c += 128) {
            float4 v = *(const float4*)(xrow + c);
            float4 g = *(const float4*)(gamma + c);
            float4 bb = *(const float4*)(beta + c);
            float4 o4;
            o4.x = (v.x - mu) * rstd * g.x + bb.x;
            o4.y = (v.y - mu) * rstd * g.y + bb.y;
            o4.z = (v.z - mu) * rstd * g.z + bb.z;
            o4.w = (v.w - mu) * rstd * g.w + bb.w;
            *(float4*)(orow + c) = o4;
        }
    }
}

// ===================== launch =====================
extern "C" void kernel_launch(void* const* d_in, const int* in_sizes, int n_in,
                              void* d_out, int out_size) {
    const float* h        = (const float*)d_in[0];
    const float* Wq       = (const float*)d_in[1];
    const float* bq       = (const float*)d_in[2];
    const float* Wk       = (const float*)d_in[3];
    const float* bk       = (const float*)d_in[4];
    const float* Wv       = (const float*)d_in[5];
    const float* bv       = (const float*)d_in[6];
    const float* Wo       = (const float*)d_in[7];
    const float* bo       = (const float*)d_in[8];
    const float* gamma    = (const float*)d_in[9];
    const float* beta     = (const float*)d_in[10];
    const float* screen_d = (const float*)d_in[11];
    const float* scale    = (const float*)d_in[12];
    const int n_screen = in_sizes[11];
    const long B = in_sizes[0] / (T_FRAMES * HID);
    const long M = B * T_FRAMES;                    // 90112
    float* out = (float*)d_out;

    cudaFuncSetAttribute(gemm_kernel, cudaFuncAttributeMaxDynamicSharedMemorySize, GEMM_SMEM);
    cudaFuncSetAttribute(attn_kernel, cudaFuncAttributeMaxDynamicSharedMemorySize, ATTN_SMEM);

    w2_part_kernel<<<dim3(HID / 64, HID / 64, 8), 256>>>(Wo, Wv);
    w2_reduce_kernel<<<(HID * HID / 4) / 256, 256>>>();
    cvec_kernel<<<HID / 256, 256>>>(Wo, bv, bo);
    prep_w_kernel<<<(NTOT * HID / 4) / 256, 256>>>(Wq, Wk, bq, bk);
    convert_h_kernel<<<(unsigned)((M * HID / 4) / 256), 256>>>(h);

    dim3 ggrid(NTOT / 128, (unsigned)(M / 128));
    gemm_kernel<<<ggrid, 256, GEMM_SMEM>>>();

    attn_kernel<<<(unsigned)B, 256, ATTN_SMEM>>>(h, gamma, beta, screen_d, n_screen, scale, out);
}

// round 6
// speedup vs baseline: 22.3959x; 1.0670x over previous
#include <cuda_runtime.h>
#include <cuda_bf16.h>
#include <cstdint>

#define T_FRAMES 11
#define HID 1024
#define NTOT 1536
#define LN_EPS 1e-5f

// ===================== device scratch =====================
#define MROWS_MAX (8192L * T_FRAMES)          // 90112
__device__ __nv_bfloat16 g_h_hi[MROWS_MAX * HID];
__device__ __nv_bfloat16 g_W_hi[NTOT * HID];
__device__ float g_w2p[8][HID * HID];          // split-K partials
__device__ float g_bias[NTOT];
__device__ __nv_bfloat16 g_qk[MROWS_MAX * 512];  // Q|K outputs, bf16
__device__ float g_x[MROWS_MAX * HID];           // X outputs, fp32

// ===================== PTX helpers (base sm_80+ features only) =====================
__device__ __forceinline__ uint32_t smem_u32(const void* p) {
    uint32_t a;
    asm("{ .reg .u64 t; cvta.to.shared.u64 t, %1; cvt.u32.u64 %0, t; }" : "=r"(a) : "l"(p));
    return a;
}
__device__ __forceinline__ void cp16(uint32_t dst, const void* src) {
    asm volatile("cp.async.cg.shared.global [%0], [%1], 16;" :: "r"(dst), "l"(src));
}
#define CP_COMMIT() asm volatile("cp.async.commit_group;" ::: "memory")
#define CP_WAIT2()  asm volatile("cp.async.wait_group 2;" ::: "memory")

__device__ __forceinline__ void ldsm4(uint32_t& r0, uint32_t& r1, uint32_t& r2, uint32_t& r3,
                                      uint32_t addr) {
    asm volatile("ldmatrix.sync.aligned.m8n8.x4.shared.b16 {%0,%1,%2,%3}, [%4];"
                 : "=r"(r0), "=r"(r1), "=r"(r2), "=r"(r3) : "r"(addr));
}
__device__ __forceinline__ void mma16816(float* c, const uint32_t* a, const uint32_t* b) {
    asm volatile(
        "mma.sync.aligned.m16n8k16.row.col.f32.bf16.bf16.f32 "
        "{%0,%1,%2,%3}, {%4,%5,%6,%7}, {%8,%9}, {%0,%1,%2,%3};"
        : "+f"(c[0]), "+f"(c[1]), "+f"(c[2]), "+f"(c[3])
        : "r"(a[0]), "r"(a[1]), "r"(a[2]), "r"(a[3]), "r"(b[0]), "r"(b[1]));
}

// ===================== h -> bf16 =====================
__global__ __launch_bounds__(256) void convert_h_kernel(const float* __restrict__ h) {
    long i = (long)blockIdx.x * 256 + threadIdx.x; // over M*HID/4 float4s
    float4 v = ((const float4*)h)[i];
    union { __nv_bfloat162 b[2]; uint2 u; } ph;
    ph.b[0] = __floats2bfloat162_rn(v.x, v.y);
    ph.b[1] = __floats2bfloat162_rn(v.z, v.w);
    ((uint2*)g_h_hi)[i] = ph.u;
}

// ===================== W2 = Wo @ Wv, split-K x8 =====================
__global__ __launch_bounds__(256) void w2_part_kernel(const float* __restrict__ Wo,
                                                      const float* __restrict__ Wv) {
    __shared__ float As[64][16];
    __shared__ float Bs[16][64];
    const int tid = threadIdx.x;
    const int tx = tid & 15, ty = tid >> 4;
    const int row0 = blockIdx.y * 64, col0 = blockIdx.x * 64;
    const int kbase = blockIdx.z * 128;
    float acc[4][4] = {};
    for (int k0 = kbase; k0 < kbase + 128; k0 += 16) {
        for (int i = tid; i < 1024; i += 256) {
            As[i >> 4][i & 15] = Wo[(size_t)(row0 + (i >> 4)) * HID + k0 + (i & 15)];
            Bs[i >> 6][i & 63] = Wv[(size_t)(k0 + (i >> 6)) * HID + col0 + (i & 63)];
        }
        __syncthreads();
        #pragma unroll
        for (int kk = 0; kk < 16; kk++) {
            float a0 = As[ty*4+0][kk], a1 = As[ty*4+1][kk], a2 = As[ty*4+2][kk], a3 = As[ty*4+3][kk];
            float4 b = *(const float4*)&Bs[kk][tx*4];
            acc[0][0]=fmaf(a0,b.x,acc[0][0]); acc[0][1]=fmaf(a0,b.y,acc[0][1]); acc[0][2]=fmaf(a0,b.z,acc[0][2]); acc[0][3]=fmaf(a0,b.w,acc[0][3]);
            acc[1][0]=fmaf(a1,b.x,acc[1][0]); acc[1][1]=fmaf(a1,b.y,acc[1][1]); acc[1][2]=fmaf(a1,b.z,acc[1][2]); acc[1][3]=fmaf(a1,b.w,acc[1][3]);
            acc[2][0]=fmaf(a2,b.x,acc[2][0]); acc[2][1]=fmaf(a2,b.y,acc[2][1]); acc[2][2]=fmaf(a2,b.z,acc[2][2]); acc[2][3]=fmaf(a2,b.w,acc[2][3]);
            acc[3][0]=fmaf(a3,b.x,acc[3][0]); acc[3][1]=fmaf(a3,b.y,acc[3][1]); acc[3][2]=fmaf(a3,b.z,acc[3][2]); acc[3][3]=fmaf(a3,b.w,acc[3][3]);
        }
        __syncthreads();
    }
    float* dst = g_w2p[blockIdx.z];
    #pragma unroll
    for (int i = 0; i < 4; i++)
        #pragma unroll
        for (int j = 0; j < 4; j++)
            dst[(size_t)(row0 + ty*4 + i) * HID + col0 + tx*4 + j] = acc[i][j];
}

// ===================== finalize W: reduce partials + convert all W to bf16 + biases ==
// blocks [0,1536): W bf16 conversion (rows<512 from Wq/Wk, rows>=512 reduce g_w2p)
// blocks [1536,1540): cvec = Wo@bv + bo into g_bias[512..]
__global__ __launch_bounds__(256) void finalize_w_kernel(const float* __restrict__ Wq,
                                                         const float* __restrict__ Wk,
                                                         const float* __restrict__ bq,
                                                         const float* __restrict__ bk,
                                                         const float* __restrict__ Wo,
                                                         const float* __restrict__ bv,
                                                         const float* __restrict__ bo) {
    if (blockIdx.x < 1536) {
        int i = blockIdx.x * 256 + threadIdx.x;        // over 1536*1024/4 float4s
        int row = i >> 8, c4 = i & 255;
        float4 v;
        if (row < 256)      v = ((const float4*)(Wq + (size_t)row * HID))[c4];
        else if (row < 512) v = ((const float4*)(Wk + (size_t)(row - 256) * HID))[c4];
        else {
            size_t off = (size_t)(row - 512) * 256 + c4;
            v = ((const float4*)g_w2p[0])[off];
            #pragma unroll
            for (int z = 1; z < 8; z++) {
                float4 p = ((const float4*)g_w2p[z])[off];
                v.x += p.x; v.y += p.y; v.z += p.z; v.w += p.w;
            }
        }
        union { __nv_bfloat162 b[2]; uint2 u; } ph;
        ph.b[0] = __floats2bfloat162_rn(v.x, v.y);
        ph.b[1] = __floats2bfloat162_rn(v.z, v.w);
        ((uint2*)g_W_hi)[i] = ph.u;
        if (i < 128)
            ((float4*)g_bias)[i] = (i < 64) ? ((const float4*)bq)[i] : ((const float4*)bk)[i - 64];
    } else {
        int o = (blockIdx.x - 1536) * 256 + threadIdx.x;   // 0..1023
        float s = 0.f;
        for (int m = 0; m < HID; m += 4) {
            float4 w = *(const float4*)(Wo + (size_t)o * HID + m);
            float4 b = *(const float4*)(bv + m);
            s = fmaf(w.x,b.x,s); s = fmaf(w.y,b.y,s); s = fmaf(w.z,b.z,s); s = fmaf(w.w,b.w,s);
        }
        g_bias[512 + o] = s + bo[o];
    }
}

// ===================== mma.sync GEMM: [QK|X] = h * W^T + bias =====================
// CTA 128x128, BK=64, 3-stage cp.async pipeline, 8 warps (2m x 4n), warp 64x32.
// n0 < 512 -> bf16 to g_qk ; n0 >= 512 -> fp32 to g_x. 2 CTAs/SM.
#define BK 64
#define NKS (HID / BK)             // 16
#define MAT_B 16384                // 128 rows x 64 bf16 = 16KB per matrix
#define STAGE_B (2 * MAT_B)        // Ah|Bh = 32KB
#define GEMM_SMEM (3 * STAGE_B)    // 96KB

__device__ __forceinline__ uint32_t swz(uint32_t byte) {
    return byte ^ ((byte >> 3) & 0x70);
}

__global__ __launch_bounds__(256, 2) void gemm_kernel() {
    extern __shared__ __align__(1024) char sm[];
    const int tid = threadIdx.x, wid = tid >> 5, lane = tid & 31;
    const long m0 = (long)blockIdx.y * 128;
    const long n0 = (long)blockIdx.x * 128;
    const int m_w = (wid & 1) * 64;       // warp M offset
    const int n_w = (wid >> 1) * 32;      // warp N offset
    const uint32_t sb = smem_u32(sm);

    const __nv_bfloat16* __restrict__ Ah = g_h_hi + m0 * HID;
    const __nv_bfloat16* __restrict__ Bh = g_W_hi + n0 * HID;

    const int crow = tid >> 3;            // base row (we add i*32)
    const int ckc  = tid & 7;             // 16B chunk within 128B row

    #pragma unroll
    for (int s = 0; s < 3; s++) {
        uint32_t st = sb + s * STAGE_B;
        int ko = s * BK;
        #pragma unroll
        for (int i = 0; i < 4; i++) {
            int row = crow + i * 32;
            uint32_t sw = swz(row * 128 + ckc * 16);
            size_t go = (size_t)row * HID + ko + ckc * 8;
            cp16(st + sw,         Ah + go);
            cp16(st + MAT_B + sw, Bh + go);
        }
        CP_COMMIT();
    }

    float acc[4][4][4] = {};   // [mt][nt][reg]

    for (int ks = 0; ks < NKS; ks++) {
        CP_WAIT2();
        __syncthreads();
        const uint32_t st = sb + (ks % 3) * STAGE_B;

        #pragma unroll
        for (int kk = 0; kk < BK / 16; kk++) {
            uint32_t ah[4][4], bh[4][2];
            #pragma unroll
            for (int mt = 0; mt < 4; mt++) {
                uint32_t byte = (uint32_t)(m_w + mt * 16 + (lane & 15)) * 128
                              + kk * 32 + ((lane >> 4) << 4);
                uint32_t sw = swz(byte);
                ldsm4(ah[mt][0], ah[mt][1], ah[mt][2], ah[mt][3], st + sw);
            }
            #pragma unroll
            for (int half = 0; half < 2; half++) {
                int grp = lane >> 3;
                uint32_t rowB = (uint32_t)(n_w + half * 16 + ((grp & 2) << 2) + (lane & 7));
                uint32_t byte = rowB * 128 + kk * 32 + ((grp & 1) << 4);
                uint32_t sw = swz(byte);
                ldsm4(bh[half*2][0], bh[half*2][1], bh[half*2+1][0], bh[half*2+1][1],
                      st + MAT_B + sw);
            }
            #pragma unroll
            for (int mt = 0; mt < 4; mt++)
                #pragma unroll
                for (int nt = 0; nt < 4; nt++)
                    mma16816(acc[mt][nt], ah[mt], bh[nt]);
        }
        __syncthreads();

        if (ks + 3 < NKS) {
            uint32_t st2 = sb + (ks % 3) * STAGE_B;
            int ko = (ks + 3) * BK;
            #pragma unroll
            for (int i = 0; i < 4; i++) {
                int row = crow + i * 32;
                uint32_t sw = swz(row * 128 + ckc * 16);
                size_t go = (size_t)row * HID + ko + ckc * 8;
                cp16(st2 + sw,         Ah + go);
                cp16(st2 + MAT_B + sw, Bh + go);
            }
        }
        CP_COMMIT();
    }

    // epilogue: D + bias
    const int qrow = lane >> 2;            // 0..7
    const int qcol = 2 * (lane & 3);       // 0,2,4,6
    if (n0 < 512) {
        // bf16 -> g_qk [M,512]
        #pragma unroll
        for (int nt = 0; nt < 4; nt++) {
            const int col = (int)n0 + n_w + nt * 8 + qcol;
            const float2 bv = *(const float2*)(g_bias + col);
            #pragma unroll
            for (int mt = 0; mt < 4; mt++) {
                long r0 = m0 + m_w + mt * 16 + qrow;
                __nv_bfloat162 v0 = __floats2bfloat162_rn(acc[mt][nt][0] + bv.x,
                                                          acc[mt][nt][1] + bv.y);
                __nv_bfloat162 v1 = __floats2bfloat162_rn(acc[mt][nt][2] + bv.x,
                                                          acc[mt][nt][3] + bv.y);
                *(__nv_bfloat162*)(g_qk + r0 * 512 + col)       = v0;
                *(__nv_bfloat162*)(g_qk + (r0 + 8) * 512 + col) = v1;
            }
        }
    } else {
        // fp32 -> g_x [M,1024]
        #pragma unroll
        for (int nt = 0; nt < 4; nt++) {
            const int colb = (int)n0 + n_w + nt * 8 + qcol;
            const float2 bv = *(const float2*)(g_bias + colb);
            const int col = colb - 512;
            #pragma unroll
            for (int mt = 0; mt < 4; mt++) {
                long r0 = m0 + m_w + mt * 16 + qrow;
                float2 v0 = { acc[mt][nt][0] + bv.x, acc[mt][nt][1] + bv.y };
                float2 v1 = { acc[mt][nt][2] + bv.x, acc[mt][nt][3] + bv.y };
                *(float2*)(g_x + r0 * HID + col)       = v0;
                *(float2*)(g_x + (r0 + 8) * HID + col) = v1;
            }
        }
    }
}

// ===================== attention + softmax + residual + LN =====================
// smem: xs [11][1024] f32 | sc [132] f32 | qk bf16 [11][520]
#define QK_STR 520
#define ATTN_SMEM (((11 * 1024 + 132) * 4) + (11 * QK_STR * 2))

__global__ __launch_bounds__(256) void attn_kernel(const float* __restrict__ h,
                                                   const float* __restrict__ gamma,
                                                   const float* __restrict__ beta,
                                                   const float* __restrict__ screen_d, int n_screen,
                                                   const float* __restrict__ scale,
                                                   float* __restrict__ out) {
    extern __shared__ float sa[];
    float* xs = sa;                          // [11][1024]
    float* sc = sa + 11 * 1024;              // [11][12]
    __nv_bfloat16* qk = (__nv_bfloat16*)(sa + 11 * 1024 + 132);  // [11][520]
    const int tid = threadIdx.x;
    const long b = blockIdx.x;
    const __nv_bfloat16* __restrict__ qkb = g_qk + b * T_FRAMES * 512;
    const float* __restrict__ xb = g_x + b * T_FRAMES * HID;
    const float* __restrict__ hb = h + b * T_FRAMES * HID;

    // load Q|K (bf16): 11 rows x 512 = 704 uint4
    for (int idx = tid; idx < 11 * 64; idx += 256) {
        int r = idx >> 6, c = idx & 63;
        *((uint4*)(qk + r * QK_STR) + c) = ((const uint4*)(qkb + r * 512))[c];
    }
    __syncthreads();

    const float scl = scale[0];
    if (tid < 121) {
        int i = tid / 11, j = tid - i * 11;
        const __nv_bfloat162* q2 = (const __nv_bfloat162*)(qk + i * QK_STR);
        const __nv_bfloat162* k2 = (const __nv_bfloat162*)(qk + j * QK_STR + 256);
        float s = 0.f;
        #pragma unroll 16
        for (int k = 0; k < 128; k++) {
            float2 a = __bfloat1622float2(q2[k]);
            float2 bb = __bfloat1622float2(k2[k]);
            s = fmaf(a.x, bb.x, s);
            s = fmaf(a.y, bb.y, s);
        }
        float r = fabsf((float)(i - j));
        float rr2 = r * r + 1e-6f;
        float wsum = 0.f, sg = 1.f;
        for (int kk = 0; kk < n_screen; kk++) {
            float d = screen_d[kk];
            wsum += sg * rsqrtf(d * d + rr2);
            sg = -sg;
        }
        sc[i * 12 + j] = s * 0.0625f + wsum / (scl + 1e-6f);
    }
    __syncthreads();

    if (tid < T_FRAMES) {
        float* row = sc + tid * 12;
        float m = row[0];
        #pragma unroll
        for (int j = 1; j < 11; j++) m = fmaxf(m, row[j]);
        float sum = 0.f;
        #pragma unroll
        for (int j = 0; j < 11; j++) { float e = expf(row[j] - m); row[j] = e; sum += e; }
        float inv = 1.f / sum;
        #pragma unroll
        for (int j = 0; j < 11; j++) row[j] *= inv;
    }
    __syncthreads();

    // x = h + P @ X
    #pragma unroll
    for (int it = 0; it < 4; it++) {
        int c = tid + it * 256;
        float xv[11];
        #pragma unroll
        for (int j = 0; j < 11; j++) xv[j] = xb[j * HID + c];
        #pragma unroll
        for (int i = 0; i < 11; i++) {
            float a = 0.f;
            #pragma unroll
            for (int j = 0; j < 11; j++) a = fmaf(sc[i * 12 + j], xv[j], a);
            xs[i * 1024 + c] = hb[i * HID + c] + a;
        }
    }
    __syncthreads();

    const int w = tid >> 5, lane = tid & 31;
    for (int rr = w; rr < T_FRAMES; rr += 8) {
        const float* xrow = xs + rr * 1024;
        float s = 0.f, s2 = 0.f;
        for (int c = lane * 4; c < HID; c += 128) {
            float4 v = *(const float4*)(xrow + c);
            s  += v.x + v.y + v.z + v.w;
            s2 += v.x*v.x + v.y*v.y + v.z*v.z + v.w*v.w;
        }
        #pragma unroll
        for (int o = 16; o > 0; o >>= 1) {
            s  += __shfl_xor_sync(0xffffffffu, s, o);
            s2 += __shfl_xor_sync(0xffffffffu, s2, o);
        }
        float mu = s * (1.f / HID);
        float var = s2 * (1.f / HID) - mu * mu;
        float rstd = rsqrtf(var + LN_EPS);
        float* orow = out + (b * T_FRAMES + rr) * HID;
        for (int c = lane * 4; c < HID; c += 128) {
            float4 v = *(const float4*)(xrow + c);
            float4 g = *(const float4*)(gamma + c);
            float4 bb = *(const float4*)(beta + c);
            float4 o4;
            o4.x = (v.x - mu) * rstd * g.x + bb.x;
            o4.y = (v.y - mu) * rstd * g.y + bb.y;
            o4.z = (v.z - mu) * rstd * g.z + bb.z;
            o4.w = (v.w - mu) * rstd * g.w + bb.w;
            *(float4*)(orow + c) = o4;
        }
    }
}

// ===================== launch =====================
extern "C" void kernel_launch(void* const* d_in, const int* in_sizes, int n_in,
                              void* d_out, int out_size) {
    const float* h        = (const float*)d_in[0];
    const float* Wq       = (const float*)d_in[1];
    const float* bq       = (const float*)d_in[2];
    const float* Wk       = (const float*)d_in[3];
    const float* bk       = (const float*)d_in[4];
    const float* Wv       = (const float*)d_in[5];
    const float* bv       = (const float*)d_in[6];
    const float* Wo       = (const float*)d_in[7];
    const float* bo       = (const float*)d_in[8];
    const float* gamma    = (const float*)d_in[9];
    const float* beta     = (const float*)d_in[10];
    const float* screen_d = (const float*)d_in[11];
    const float* scale    = (const float*)d_in[12];
    const int n_screen = in_sizes[11];
    const long B = in_sizes[0] / (T_FRAMES * HID);
    const long M = B * T_FRAMES;                    // 90112
    float* out = (float*)d_out;

    cudaFuncSetAttribute(gemm_kernel, cudaFuncAttributeMaxDynamicSharedMemorySize, GEMM_SMEM);
    cudaFuncSetAttribute(attn_kernel, cudaFuncAttributeMaxDynamicSharedMemorySize, ATTN_SMEM);

    convert_h_kernel<<<(unsigned)((M * HID / 4) / 256), 256>>>(h);
    w2_part_kernel<<<dim3(HID / 64, HID / 64, 8), 256>>>(Wo, Wv);
    finalize_w_kernel<<<1536 + 4, 256>>>(Wq, Wk, bq, bk, Wo, bv, bo);

    dim3 ggrid(NTOT / 128, (unsigned)(M / 128));
    gemm_kernel<<<ggrid, 256, GEMM_SMEM>>>();

    attn_kernel<<<(unsigned)B, 256, ATTN_SMEM>>>(h, gamma, beta, screen_d, n_screen, scale, out);
}